// round 12
// baseline (speedup 1.0000x reference)
#include <cuda_runtime.h>

// Device-global for the 4x4 doubly-stochastic matrix H (16B-aligned for LDG.128).
__device__ __align__(16) float g_H[16];

__device__ __forceinline__ float rcp_approx(float x) {
    float r;
    asm("rcp.approx.f32 %0, %1;" : "=f"(r) : "f"(x));
    return r;
}

__device__ __forceinline__ void stwt_f4(float4* p, float4 v) {
    asm volatile("st.global.wt.v4.f32 [%0], {%1, %2, %3, %4};"
                 :: "l"(p), "f"(v.x), "f"(v.y), "f"(v.z), "f"(v.w) : "memory");
}

// ---------------------------------------------------------------------------
// Kernel 1: single-thread Sinkhorn with row/col ILP and rcp.approx (~0.6us).
// PDL trigger after fenced g_H writes.
// ---------------------------------------------------------------------------
__global__ void sinkhorn_kernel(const float* __restrict__ H_raw) {
    if (threadIdx.x == 0) {
        float A[16];
        #pragma unroll
        for (int i = 0; i < 16; i++) A[i] = fabsf(__ldg(&H_raw[i])) + 1e-8f;

        #pragma unroll 1
        for (int it = 0; it < 20; it++) {
            #pragma unroll
            for (int i = 0; i < 4; i++) {
                float s = (A[4*i+0] + A[4*i+1]) + (A[4*i+2] + A[4*i+3]);
                float inv = rcp_approx(s);
                #pragma unroll
                for (int j = 0; j < 4; j++) A[4*i+j] *= inv;
            }
            #pragma unroll
            for (int j = 0; j < 4; j++) {
                float s = (A[0+j] + A[4+j]) + (A[8+j] + A[12+j]);
                float inv = rcp_approx(s);
                #pragma unroll
                for (int i = 0; i < 4; i++) A[4*i+j] *= inv;
            }
        }
        #pragma unroll
        for (int i = 0; i < 16; i++) g_H[i] = A[i];
        __threadfence();
    }
    cudaTriggerProgrammaticLaunchCompletion();
}

// ---------------------------------------------------------------------------
// Kernel 2: streaming mix — R11's winning geometry (512 threads, 4 bt rows
// per block, grid 4096; 8 front-batched float4 __ldcs loads MLP=8; H via
// 4x LDG.128), with write-through (st.global.wt) stores: output is never
// re-read, so skip L2 dirty-line retention on the store stream.
//   out[bt, n, d] = sum_m H[n,m] * x[bt, m, d]
// ---------------------------------------------------------------------------
__global__ __launch_bounds__(512) void mix_kernel(const float4* __restrict__ x,
                                                  float4* __restrict__ out) {
    const int q    = threadIdx.x & 255;          // float4 lane within a row
    const int half = threadIdx.x >> 8;           // 0 or 1: which row-pair
    const size_t bt0 = (size_t)blockIdx.x * 4 + half * 2;

    const float4* __restrict__ xa = x + bt0 * 1024;
    const float4* __restrict__ xb = xa + 1024;
    float4* __restrict__ oa       = out + bt0 * 1024;
    float4* __restrict__ ob       = oa + 1024;

    // Front-batch all 8 stream loads (MLP=8), evict-first.
    float4 a0 = __ldcs(xa + 0 * 256 + q);
    float4 a1 = __ldcs(xa + 1 * 256 + q);
    float4 a2 = __ldcs(xa + 2 * 256 + q);
    float4 a3 = __ldcs(xa + 3 * 256 + q);
    float4 b0 = __ldcs(xb + 0 * 256 + q);
    float4 b1 = __ldcs(xb + 1 * 256 + q);
    float4 b2 = __ldcs(xb + 2 * 256 + q);
    float4 b3 = __ldcs(xb + 3 * 256 + q);

    // Wait for the sinkhorn kernel's trigger (overlapped with loads above).
    cudaGridDependencySynchronize();

    // H as 4 vectorized broadcast loads (rows of H).
    const float4* __restrict__ Hv = (const float4*)g_H;
    float4 hr[4];
    #pragma unroll
    for (int n = 0; n < 4; n++) hr[n] = __ldg(&Hv[n]);

    #pragma unroll
    for (int n = 0; n < 4; n++) {
        const float h0 = hr[n].x, h1 = hr[n].y, h2 = hr[n].z, h3 = hr[n].w;
        float4 o;
        o.x = h0 * a0.x + h1 * a1.x + h2 * a2.x + h3 * a3.x;
        o.y = h0 * a0.y + h1 * a1.y + h2 * a2.y + h3 * a3.y;
        o.z = h0 * a0.z + h1 * a1.z + h2 * a2.z + h3 * a3.z;
        o.w = h0 * a0.w + h1 * a1.w + h2 * a2.w + h3 * a3.w;
        stwt_f4(oa + n * 256 + q, o);
    }
    #pragma unroll
    for (int n = 0; n < 4; n++) {
        const float h0 = hr[n].x, h1 = hr[n].y, h2 = hr[n].z, h3 = hr[n].w;
        float4 o;
        o.x = h0 * b0.x + h1 * b1.x + h2 * b2.x + h3 * b3.x;
        o.y = h0 * b0.y + h1 * b1.y + h2 * b2.y + h3 * b3.y;
        o.z = h0 * b0.z + h1 * b1.z + h2 * b2.z + h3 * b3.z;
        o.w = h0 * b0.w + h1 * b1.w + h2 * b2.w + h3 * b3.w;
        stwt_f4(ob + n * 256 + q, o);
    }
}

extern "C" void kernel_launch(void* const* d_in, const int* in_sizes, int n_in,
                              void* d_out, int out_size) {
    const float* x     = (const float*)d_in[0];  // [4, 4096, 4, 1024] fp32
    const float* H_raw = (const float*)d_in[1];  // [4, 4]
    float* out         = (float*)d_out;          // same shape as x

    sinkhorn_kernel<<<1, 32>>>(H_raw);

    const int BT = 4 * 4096;  // 16384 (b,t) pairs, 4 per block

    cudaLaunchConfig_t cfg = {};
    cfg.gridDim  = dim3(BT / 4, 1, 1);
    cfg.blockDim = dim3(512, 1, 1);
    cfg.dynamicSmemBytes = 0;
    cfg.stream = 0;
    cudaLaunchAttribute attr[1];
    attr[0].id = cudaLaunchAttributeProgrammaticStreamSerialization;
    attr[0].val.programmaticStreamSerializationAllowed = 1;
    cfg.attrs = attr;
    cfg.numAttrs = 1;

    cudaLaunchKernelEx(&cfg, mix_kernel, (const float4*)x, (float4*)out);
    (void)in_sizes; (void)n_in; (void)out_size;
}

// round 13
// speedup vs baseline: 1.0193x; 1.0193x over previous
#include <cuda_runtime.h>

// Device-global for the 4x4 doubly-stochastic matrix H (16B-aligned for LDG.128).
__device__ __align__(16) float g_H[16];

__device__ __forceinline__ float rcp_approx(float x) {
    float r;
    asm("rcp.approx.f32 %0, %1;" : "=f"(r) : "f"(x));
    return r;
}

// ---------------------------------------------------------------------------
// Kernel 1: single-thread Sinkhorn with row/col ILP and rcp.approx (~0.6us).
// PDL trigger after fenced g_H writes.
// ---------------------------------------------------------------------------
__global__ void sinkhorn_kernel(const float* __restrict__ H_raw) {
    if (threadIdx.x == 0) {
        float A[16];
        #pragma unroll
        for (int i = 0; i < 16; i++) A[i] = fabsf(__ldg(&H_raw[i])) + 1e-8f;

        #pragma unroll 1
        for (int it = 0; it < 20; it++) {
            #pragma unroll
            for (int i = 0; i < 4; i++) {
                float s = (A[4*i+0] + A[4*i+1]) + (A[4*i+2] + A[4*i+3]);
                float inv = rcp_approx(s);
                #pragma unroll
                for (int j = 0; j < 4; j++) A[4*i+j] *= inv;
            }
            #pragma unroll
            for (int j = 0; j < 4; j++) {
                float s = (A[0+j] + A[4+j]) + (A[8+j] + A[12+j]);
                float inv = rcp_approx(s);
                #pragma unroll
                for (int i = 0; i < 4; i++) A[4*i+j] *= inv;
            }
        }
        #pragma unroll
        for (int i = 0; i < 16; i++) g_H[i] = A[i];
        __threadfence();
    }
    cudaTriggerProgrammaticLaunchCompletion();
}

// ---------------------------------------------------------------------------
// Kernel 2: streaming mix — converged optimum (R11):
//   * 512 threads / 4 bt rows per block (grid 4096)
//   * 8 front-batched float4 __ldcs loads per thread (MLP=8, evict-first)
//   * __stcs stores (evict-first; beats default and write-through)
//   * H via 4x LDG.128 broadcast loads
//   * loads issued before cudaGridDependencySynchronize() (PDL overlap)
//   out[bt, n, d] = sum_m H[n,m] * x[bt, m, d]
// ---------------------------------------------------------------------------
__global__ __launch_bounds__(512) void mix_kernel(const float4* __restrict__ x,
                                                  float4* __restrict__ out) {
    const int q    = threadIdx.x & 255;          // float4 lane within a row
    const int half = threadIdx.x >> 8;           // 0 or 1: which row-pair
    const size_t bt0 = (size_t)blockIdx.x * 4 + half * 2;

    const float4* __restrict__ xa = x + bt0 * 1024;
    const float4* __restrict__ xb = xa + 1024;
    float4* __restrict__ oa       = out + bt0 * 1024;
    float4* __restrict__ ob       = oa + 1024;

    // Front-batch all 8 stream loads (MLP=8), evict-first.
    float4 a0 = __ldcs(xa + 0 * 256 + q);
    float4 a1 = __ldcs(xa + 1 * 256 + q);
    float4 a2 = __ldcs(xa + 2 * 256 + q);
    float4 a3 = __ldcs(xa + 3 * 256 + q);
    float4 b0 = __ldcs(xb + 0 * 256 + q);
    float4 b1 = __ldcs(xb + 1 * 256 + q);
    float4 b2 = __ldcs(xb + 2 * 256 + q);
    float4 b3 = __ldcs(xb + 3 * 256 + q);

    // Wait for the sinkhorn kernel's trigger (overlapped with loads above).
    cudaGridDependencySynchronize();

    // H as 4 vectorized broadcast loads (rows of H).
    const float4* __restrict__ Hv = (const float4*)g_H;
    float4 hr[4];
    #pragma unroll
    for (int n = 0; n < 4; n++) hr[n] = __ldg(&Hv[n]);

    #pragma unroll
    for (int n = 0; n < 4; n++) {
        const float h0 = hr[n].x, h1 = hr[n].y, h2 = hr[n].z, h3 = hr[n].w;
        float4 o;
        o.x = h0 * a0.x + h1 * a1.x + h2 * a2.x + h3 * a3.x;
        o.y = h0 * a0.y + h1 * a1.y + h2 * a2.y + h3 * a3.y;
        o.z = h0 * a0.z + h1 * a1.z + h2 * a2.z + h3 * a3.z;
        o.w = h0 * a0.w + h1 * a1.w + h2 * a2.w + h3 * a3.w;
        __stcs(oa + n * 256 + q, o);
    }
    #pragma unroll
    for (int n = 0; n < 4; n++) {
        const float h0 = hr[n].x, h1 = hr[n].y, h2 = hr[n].z, h3 = hr[n].w;
        float4 o;
        o.x = h0 * b0.x + h1 * b1.x + h2 * b2.x + h3 * b3.x;
        o.y = h0 * b0.y + h1 * b1.y + h2 * b2.y + h3 * b3.y;
        o.z = h0 * b0.z + h1 * b1.z + h2 * b2.z + h3 * b3.z;
        o.w = h0 * b0.w + h1 * b1.w + h2 * b2.w + h3 * b3.w;
        __stcs(ob + n * 256 + q, o);
    }
}

extern "C" void kernel_launch(void* const* d_in, const int* in_sizes, int n_in,
                              void* d_out, int out_size) {
    const float* x     = (const float*)d_in[0];  // [4, 4096, 4, 1024] fp32
    const float* H_raw = (const float*)d_in[1];  // [4, 4]
    float* out         = (float*)d_out;          // same shape as x

    sinkhorn_kernel<<<1, 32>>>(H_raw);

    const int BT = 4 * 4096;  // 16384 (b,t) pairs, 4 per block

    cudaLaunchConfig_t cfg = {};
    cfg.gridDim  = dim3(BT / 4, 1, 1);
    cfg.blockDim = dim3(512, 1, 1);
    cfg.dynamicSmemBytes = 0;
    cfg.stream = 0;
    cudaLaunchAttribute attr[1];
    attr[0].id = cudaLaunchAttributeProgrammaticStreamSerialization;
    attr[0].val.programmaticStreamSerializationAllowed = 1;
    cfg.attrs = attr;
    cfg.numAttrs = 1;

    cudaLaunchKernelEx(&cfg, mix_kernel, (const float4*)x, (float4*)out);
    (void)in_sizes; (void)n_in; (void)out_size;
}